// round 12
// baseline (speedup 1.0000x reference)
#include <cuda_runtime.h>
#include <cuda_fp16.h>
#include <cstdint>

// ---------------------------------------------------------------------------
// MultiShapeNet: h = sin(x@Wpre + bpre); 8 blocks of
//   h = gamma*h + beta;  r = sin(h@W0+b0); r = sin(r@W1+b1); h = 0.5*(h+r)
// N=262144, HIDDEN=128, fp32 in/out, rel_err < 1e-3.
//
// R12: 2-term split.  r = Ahi*Whi + Alo*Whi  ( == A * fp16(W) exactly up to
// fp32 accum).  Only approximation = dropping A*Wlo; analysis gives ~2e-4
// total rel err (residual halving damps accumulation).  Cuts MMAs 33% and
// weight crossbar traffic 50% vs the 3-term R11 kernel.  Weight ring deepens
// to 4 buffers (hi-only = 34KB/layer).
// ---------------------------------------------------------------------------

#define NLAY      16
#define WPAD      136           // halves per padded weight row
#define W_PITCH_B (WPAD*2)      // 272 bytes
#define WBUF_B    (128*W_PITCH_B)   // 34816 bytes per layer (hi only)
#define NBUF      4

// smem layout (bytes)
#define SM_W      0                          // 4 * 34816 = 139264
#define SM_BB     (NBUF*WBUF_B)              // 139264 : 16*128 fp32 = 8192
#define SM_WPRE   (SM_BB + 8192)             // 147456 : 512 fp32
#define SM_BPRE   (SM_WPRE + 2048)           // 149504 : 128 fp32
#define SM_MBAR   (SM_BPRE + 512)            // 150016 : 8 mbarriers
#define SMEM_TOTAL (SM_MBAR + 64)            // 150080

// weights scratch: [L][hi 34816B], rows padded to 136 halves
__device__ unsigned char g_W[NLAY * WBUF_B];

// ---------------------------------------------------------------------------
// prep: W_blocks [16][128][128] fp32 -> fp16 (hi), padded rows
// ---------------------------------------------------------------------------
__global__ void msnet_prep_kernel(const float* __restrict__ Wb) {
    int t = blockIdx.x * blockDim.x + threadIdx.x;
    if (t < NLAY*128*128) {
        int L = t >> 14;
        int k = (t >> 7) & 127;
        int n = t & 127;
        __half* base = (__half*)(g_W + (size_t)L * WBUF_B);
        base[k*WPAD + n] = __float2half_rn(Wb[t]);
    }
    if (t < NLAY*128*8) {        // zero pad columns 128..135
        int L = t >> 10;
        int k = (t >> 3) & 127;
        int n = 128 + (t & 7);
        __half* base = (__half*)(g_W + (size_t)L * WBUF_B);
        base[k*WPAD + n] = __float2half_rn(0.f);
    }
}

// ---------------------------------------------------------------------------
// PTX helpers
// ---------------------------------------------------------------------------
#define LDSM_T4(r0,r1,r2,r3,addr) \
    asm volatile("ldmatrix.sync.aligned.m8n8.x4.trans.shared.b16 {%0,%1,%2,%3},[%4];\n" \
                 : "=r"(r0), "=r"(r1), "=r"(r2), "=r"(r3) : "r"(addr))

#define MMA16816(d0,d1,d2,d3,a0,a1,a2,a3,b0,b1) \
    asm volatile("mma.sync.aligned.m16n8k16.row.col.f32.f16.f16.f32 " \
                 "{%0,%1,%2,%3},{%4,%5,%6,%7},{%8,%9},{%0,%1,%2,%3};\n" \
                 : "+f"(d0), "+f"(d1), "+f"(d2), "+f"(d3) \
                 : "r"(a0), "r"(a1), "r"(a2), "r"(a3), "r"(b0), "r"(b1))

#define MBAR_INIT(mb, cnt) \
    asm volatile("mbarrier.init.shared.b64 [%0], %1;" :: "r"((uint32_t)(mb)), "r"((uint32_t)(cnt)) : "memory")
#define MBAR_EXPECT_TX(mb, b) \
    asm volatile("mbarrier.arrive.expect_tx.shared.b64 _, [%0], %1;" :: "r"((uint32_t)(mb)), "r"((uint32_t)(b)) : "memory")
#define MBAR_ARRIVE(mb) \
    asm volatile("mbarrier.arrive.shared.b64 _, [%0];" :: "r"((uint32_t)(mb)) : "memory")

__device__ __forceinline__ void mbar_wait(uint32_t mb, uint32_t parity) {
    asm volatile(
        "{.reg .pred P;\n"
        "W%=:\n"
        "mbarrier.try_wait.parity.acquire.cta.shared::cta.b64 P, [%0], %1, 0x989680;\n"
        "@P bra.uni D%=;\n"
        "bra.uni W%=;\n"
        "D%=:\n}"
        :: "r"(mb), "r"(parity) : "memory");
}

__device__ __forceinline__ void bulkcp(uint32_t dst, const void* src, uint32_t bytes, uint32_t mb) {
    unsigned long long g = (unsigned long long)__cvta_generic_to_global(src);
    asm volatile("cp.async.bulk.shared::cta.global.mbarrier::complete_tx::bytes [%0], [%1], %2, [%3];"
                 :: "r"(dst), "l"(g), "r"(bytes), "r"(mb) : "memory");
}

__device__ __forceinline__ void pfL2(const void* p) {
    asm volatile("prefetch.global.L2 [%0];" :: "l"(p));
}

// split two fp32 into packed half2 hi + half2 lo (A-side, lossless pair)
__device__ __forceinline__ void split2(float a, float b, uint32_t& hi, uint32_t& lo) {
    __half2 h = __floats2half2_rn(a, b);
    float2 f = __half22float2(h);
    __half2 l = __floats2half2_rn(a - f.x, b - f.y);
    hi = *reinterpret_cast<uint32_t*>(&h);
    lo = *reinterpret_cast<uint32_t*>(&l);
}

// Quarter-GEMM: n-tile-pairs NTP0, NTP0+1 (N=32 cols), all 8 K-chunks,
// 2-term split (Ahi*Whi + Alo*Whi).  All indices compile-time.
__device__ __forceinline__ void gemm_q(
    const uint32_t fhi[8][4], const uint32_t flo[8][4],
    uint32_t whi_base, int NTP0, float (*acc)[4])
{
    #pragma unroll
    for (int kc = 0; kc < 8; kc++) {
        #pragma unroll
        for (int i = 0; i < 2; i++) {
            int ntp = NTP0 + i;
            uint32_t ah = whi_base + (uint32_t)(ntp*32 + kc*16*W_PITCH_B);
            uint32_t h0, h1, h2, h3;
            LDSM_T4(h0, h1, h2, h3, ah);
            int na = 2*i, nb = 2*i + 1;
            MMA16816(acc[na][0],acc[na][1],acc[na][2],acc[na][3],
                     fhi[kc][0],fhi[kc][1],fhi[kc][2],fhi[kc][3], h0,h1);
            MMA16816(acc[nb][0],acc[nb][1],acc[nb][2],acc[nb][3],
                     fhi[kc][0],fhi[kc][1],fhi[kc][2],fhi[kc][3], h2,h3);
            MMA16816(acc[na][0],acc[na][1],acc[na][2],acc[na][3],
                     flo[kc][0],flo[kc][1],flo[kc][2],flo[kc][3], h0,h1);
            MMA16816(acc[nb][0],acc[nb][1],acc[nb][2],acc[nb][3],
                     flo[kc][0],flo[kc][1],flo[kc][2],flo[kc][3], h2,h3);
        }
    }
}

#define SIN_Q(acc, q) do {                                                    \
    _Pragma("unroll")                                                         \
    for (int nt = 4*(q); nt < 4*(q)+4; nt++) {                                \
        (acc)[nt][0] = __sinf((acc)[nt][0]);                                  \
        (acc)[nt][1] = __sinf((acc)[nt][1]);                                  \
        (acc)[nt][2] = __sinf((acc)[nt][2]);                                  \
        (acc)[nt][3] = __sinf((acc)[nt][3]);                                  \
    }                                                                         \
} while (0)

// ---------------------------------------------------------------------------
// main fused kernel: 256 threads, 128 rows per CTA
// ---------------------------------------------------------------------------
__global__ void __launch_bounds__(256, 1) msnet_kernel(
    const float* __restrict__ x,
    const float* __restrict__ gammas,
    const float* __restrict__ betas,
    const float* __restrict__ W_pre,
    const float* __restrict__ b_pre,
    const float* __restrict__ b_blocks,
    float* __restrict__ out)
{
    extern __shared__ char smem[];
    uint32_t sb = (uint32_t)__cvta_generic_to_shared(smem);

    int tid  = threadIdx.x;
    int lane = tid & 31;
    int warp = tid >> 5;
    int gr = lane >> 2;            // group row 0..7
    int gc = (lane & 3) * 2;       // group col {0,2,4,6}

    int p0 = blockIdx.x * 128 + warp * 16 + gr;
    int p1 = p0 + 8;

    uint32_t lane_off = (uint32_t)((lane & 15) * W_PITCH_B + (lane >> 4) * 16);

    if (tid == 0) {
        #pragma unroll
        for (int b = 0; b < NBUF; b++) {
            MBAR_INIT(sb + SM_MBAR + b*8, 1);        // FULL[b]
            MBAR_INIT(sb + SM_MBAR + 32 + b*8, 256); // EMPTY[b]
        }
    }

    float* sWpre = (float*)(smem + SM_WPRE);
    float* sBpre = (float*)(smem + SM_BPRE);
    float* sBB   = (float*)(smem + SM_BB);
    for (int i = tid; i < 512; i += 256) sWpre[i] = W_pre[i];
    if (tid < 128) sBpre[tid] = b_pre[tid];
    for (int i = tid; i < NLAY*128; i += 256) sBB[i] = b_blocks[i];
    __syncthreads();   // mbar init + staging visible

    // kick TMA loads for layers 0..3
    if (tid == 0) {
        #pragma unroll
        for (int b = 0; b < NBUF; b++) {
            MBAR_EXPECT_TX(sb + SM_MBAR + b*8, WBUF_B);
            bulkcp(sb + SM_W + (uint32_t)b*WBUF_B, g_W + (size_t)b*WBUF_B,
                   WBUF_B, sb + SM_MBAR + b*8);
        }
    }

    // --- pre-layer: h = sin(x @ Wpre + bpre) ---
    float4 xva = ((const float4*)x)[p0];
    float4 xvb = ((const float4*)x)[p1];
    float xr0[4] = {xva.x, xva.y, xva.z, xva.w};
    float xr1[4] = {xvb.x, xvb.y, xvb.z, xvb.w};

    float h[16][4];
    #pragma unroll
    for (int nt = 0; nt < 16; nt++) {
        int c = nt * 8 + gc;
        float t0 = sBpre[c], t1 = sBpre[c+1];
        float t2 = t0, t3 = t1;
        #pragma unroll
        for (int d = 0; d < 4; d++) {
            float w0 = sWpre[d*128 + c], w1 = sWpre[d*128 + c + 1];
            t0 = fmaf(xr0[d], w0, t0); t1 = fmaf(xr0[d], w1, t1);
            t2 = fmaf(xr1[d], w0, t2); t3 = fmaf(xr1[d], w1, t3);
        }
        h[nt][0] = __sinf(t0); h[nt][1] = __sinf(t1);
        h[nt][2] = __sinf(t2); h[nt][3] = __sinf(t3);
    }

    uint32_t fhi[8][4], flo[8][4];
    bool rev = (warp >> 2) & 1;    // warps 4-7: quarters in reverse order

    #pragma unroll 1
    for (int L = 0; L < NLAY; L++) {
        int b = L & 3;
        uint32_t up = (uint32_t)((L >> 2) & 1);
        uint32_t FULLb  = sb + SM_MBAR + (uint32_t)b*8;
        uint32_t EMPTYb = sb + SM_MBAR + 32 + (uint32_t)b*8;

        if ((L & 1) == 0) {
            int blk = L >> 1;
            // ---- FiLM: f = gamma*h + beta; h <- f (registers); split ----
            const float* gP0 = gammas + (size_t)p0 * 1024 + blk * 128;
            const float* gP1 = gammas + (size_t)p1 * 1024 + blk * 128;
            const float* bP0 = betas  + (size_t)p0 * 1024 + blk * 128;
            const float* bP1 = betas  + (size_t)p1 * 1024 + blk * 128;
            #pragma unroll
            for (int nt = 0; nt < 16; nt++) {
                int c = nt * 8 + gc;
                float2 g0 = __ldcs((const float2*)(gP0 + c));
                float2 g1 = __ldcs((const float2*)(gP1 + c));
                float2 e0 = __ldcs((const float2*)(bP0 + c));
                float2 e1 = __ldcs((const float2*)(bP1 + c));
                h[nt][0] = fmaf(g0.x, h[nt][0], e0.x);
                h[nt][1] = fmaf(g0.y, h[nt][1], e0.y);
                h[nt][2] = fmaf(g1.x, h[nt][2], e1.x);
                h[nt][3] = fmaf(g1.y, h[nt][3], e1.y);
                int kc = nt >> 1, e = (nt & 1) * 2;
                split2(h[nt][0], h[nt][1], fhi[kc][e],   flo[kc][e]);
                split2(h[nt][2], h[nt][3], fhi[kc][e+1], flo[kc][e+1]);
            }
            // L2-prefetch next block's FiLM rows (consumed in ~2 layers)
            if (blk < 7) {
                int co = (lane & 3) * 32;
                pfL2(gammas + (size_t)p0 * 1024 + (blk+1) * 128 + co);
                pfL2(gammas + (size_t)p1 * 1024 + (blk+1) * 128 + co);
                pfL2(betas  + (size_t)p0 * 1024 + (blk+1) * 128 + co);
                pfL2(betas  + (size_t)p1 * 1024 + (blk+1) * 128 + co);
            }
        }

        // ---- bias init from smem ----
        float acc[16][4];
        const float* bias = sBB + L * 128;
        #pragma unroll
        for (int nt = 0; nt < 16; nt++) {
            float2 b2 = *(const float2*)(bias + nt*8 + gc);
            acc[nt][0] = b2.x; acc[nt][1] = b2.y;
            acc[nt][2] = b2.x; acc[nt][3] = b2.y;
        }

        mbar_wait(FULLb, up);
        uint32_t wb = sb + SM_W + (uint32_t)b * WBUF_B + lane_off;

        // ---- GEMM in 4 quarters; sins of quarter q-1 interleave quarter q ----
        if (!rev) {
            gemm_q(fhi, flo, wb, 0, &acc[0]);
            gemm_q(fhi, flo, wb, 2, &acc[4]);  SIN_Q(acc, 0);
            gemm_q(fhi, flo, wb, 4, &acc[8]);  SIN_Q(acc, 1);
            gemm_q(fhi, flo, wb, 6, &acc[12]); SIN_Q(acc, 2);
            MBAR_ARRIVE(EMPTYb);
            SIN_Q(acc, 3);
        } else {
            gemm_q(fhi, flo, wb, 6, &acc[12]);
            gemm_q(fhi, flo, wb, 4, &acc[8]);  SIN_Q(acc, 3);
            gemm_q(fhi, flo, wb, 2, &acc[4]);  SIN_Q(acc, 2);
            gemm_q(fhi, flo, wb, 0, &acc[0]);  SIN_Q(acc, 1);
            MBAR_ARRIVE(EMPTYb);
            SIN_Q(acc, 0);
        }

        if ((L & 1) == 0) {
            // r1 -> fragments for layer L+1
            #pragma unroll
            for (int nt = 0; nt < 16; nt++) {
                int kc = nt >> 1, e = (nt & 1) * 2;
                split2(acc[nt][0], acc[nt][1], fhi[kc][e],   flo[kc][e]);
                split2(acc[nt][2], acc[nt][3], fhi[kc][e+1], flo[kc][e+1]);
            }
        } else {
            // residual merge: h = 0.5*(f + r2), f is current h
            #pragma unroll
            for (int nt = 0; nt < 16; nt++) {
                h[nt][0] = 0.5f * (h[nt][0] + acc[nt][0]);
                h[nt][1] = 0.5f * (h[nt][1] + acc[nt][1]);
                h[nt][2] = 0.5f * (h[nt][2] + acc[nt][2]);
                h[nt][3] = 0.5f * (h[nt][3] + acc[nt][3]);
            }
        }

        // refill buffer b with layer L+4 once all warps done reading layer L
        if (tid == 0 && L < NLAY - NBUF) {
            mbar_wait(EMPTYb, up);
            MBAR_EXPECT_TX(FULLb, WBUF_B);
            bulkcp(sb + SM_W + (uint32_t)b * WBUF_B,
                   g_W + (size_t)(L + NBUF) * WBUF_B, WBUF_B, FULLb);
        }
    }

    // ---- write output [N,128] fp32 ----
    #pragma unroll
    for (int nt = 0; nt < 16; nt++) {
        int c = nt * 8 + gc;
        *(float2*)&out[(size_t)p0 * 128 + c] = make_float2(h[nt][0], h[nt][1]);
        *(float2*)&out[(size_t)p1 * 128 + c] = make_float2(h[nt][2], h[nt][3]);
    }
}

// ---------------------------------------------------------------------------
extern "C" void kernel_launch(void* const* d_in, const int* in_sizes, int n_in,
                              void* d_out, int out_size) {
    const float* x        = (const float*)d_in[0];
    const float* gammas   = (const float*)d_in[1];
    const float* betas    = (const float*)d_in[2];
    const float* W_pre    = (const float*)d_in[3];
    const float* b_pre    = (const float*)d_in[4];
    const float* W_blocks = (const float*)d_in[5];
    const float* b_blocks = (const float*)d_in[6];
    float* out = (float*)d_out;

    int N = in_sizes[0] / 4;   // 262144

    msnet_prep_kernel<<<(NLAY*128*128 + 255) / 256, 256>>>(W_blocks);

    cudaFuncSetAttribute(msnet_kernel,
                         cudaFuncAttributeMaxDynamicSharedMemorySize, SMEM_TOTAL);
    msnet_kernel<<<N / 128, 256, SMEM_TOTAL>>>(
        x, gammas, betas, W_pre, b_pre, b_blocks, out);
}

// round 13
// speedup vs baseline: 1.3974x; 1.3974x over previous
#include <cuda_runtime.h>
#include <cuda_fp16.h>
#include <cstdint>

// ---------------------------------------------------------------------------
// MultiShapeNet: h = sin(x@Wpre + bpre); 8 blocks of
//   h = gamma*h + beta;  r = sin(h@W0+b0); r = sin(r@W1+b1); h = 0.5*(h+r)
// N=262144, HIDDEN=128, fp32 in/out, rel_err < 1e-3.
//
// R13: W-side 2-term split:  r = Ahi*Whi + Ahi*Wlo  (== fp16(A) * W).
// Dropped term Alo*W has RMS ~1.75e-5/product -> ~1.7e-4 total (calibrated
// against R12's measured 3.16e-4 for the W-side drop). Key win vs R12: the
// A-lo fragment array disappears (-32 regs from the 255-reg ceiling) and
// fragment construction is a single cvt -> ptxas scheduling headroom.
// Base structure = R9 (half-split GEMM, 3-buffer TMA ring, 1179us).
// ---------------------------------------------------------------------------

#define NLAY      16
#define WPAD      136           // halves per padded weight row
#define W_PITCH_B (WPAD*2)      // 272 bytes
#define WBUF_B    (128*W_PITCH_B)   // 34816 bytes per (hi or lo) matrix
#define WLAYER_B  (2*WBUF_B)        // 69632 bytes per layer (hi+lo)
#define NBUF      3

// smem layout (bytes)
#define SM_W      0                          // 3 * 69632 = 208896
#define SM_BB     (NBUF*WLAYER_B)            // 208896 : 16*128 fp32 = 8192
#define SM_WPRE   (SM_BB + 8192)             // 217088 : 512 fp32
#define SM_BPRE   (SM_WPRE + 2048)           // 219136 : 128 fp32
#define SM_MBAR   (SM_BPRE + 512)            // 219648 : 6 mbarriers
#define SMEM_TOTAL (SM_MBAR + 64)            // 219712

// weights scratch: [L][hi 34816B][lo 34816B], rows padded to 136 halves
__device__ unsigned char g_W[NLAY * WLAYER_B];

// ---------------------------------------------------------------------------
// prep: W_blocks [16][128][128] fp32 -> fp16 hi/lo, padded rows
// ---------------------------------------------------------------------------
__global__ void msnet_prep_kernel(const float* __restrict__ Wb) {
    int t = blockIdx.x * blockDim.x + threadIdx.x;
    if (t < NLAY*128*128) {
        int L = t >> 14;
        int k = (t >> 7) & 127;
        int n = t & 127;
        float w = Wb[t];
        __half hi = __float2half_rn(w);
        __half lo = __float2half_rn(w - __half2float(hi));
        __half* base = (__half*)(g_W + (size_t)L * WLAYER_B);
        base[k*WPAD + n] = hi;
        base[(WBUF_B/2) + k*WPAD + n] = lo;
    }
    if (t < NLAY*128*8) {        // zero pad columns 128..135
        int L = t >> 10;
        int k = (t >> 3) & 127;
        int n = 128 + (t & 7);
        __half* base = (__half*)(g_W + (size_t)L * WLAYER_B);
        base[k*WPAD + n] = __float2half_rn(0.f);
        base[(WBUF_B/2) + k*WPAD + n] = __float2half_rn(0.f);
    }
}

// ---------------------------------------------------------------------------
// PTX helpers
// ---------------------------------------------------------------------------
#define LDSM_T4(r0,r1,r2,r3,addr) \
    asm volatile("ldmatrix.sync.aligned.m8n8.x4.trans.shared.b16 {%0,%1,%2,%3},[%4];\n" \
                 : "=r"(r0), "=r"(r1), "=r"(r2), "=r"(r3) : "r"(addr))

#define MMA16816(d0,d1,d2,d3,a0,a1,a2,a3,b0,b1) \
    asm volatile("mma.sync.aligned.m16n8k16.row.col.f32.f16.f16.f32 " \
                 "{%0,%1,%2,%3},{%4,%5,%6,%7},{%8,%9},{%0,%1,%2,%3};\n" \
                 : "+f"(d0), "+f"(d1), "+f"(d2), "+f"(d3) \
                 : "r"(a0), "r"(a1), "r"(a2), "r"(a3), "r"(b0), "r"(b1))

#define MBAR_INIT(mb, cnt) \
    asm volatile("mbarrier.init.shared.b64 [%0], %1;" :: "r"((uint32_t)(mb)), "r"((uint32_t)(cnt)) : "memory")
#define MBAR_EXPECT_TX(mb, b) \
    asm volatile("mbarrier.arrive.expect_tx.shared.b64 _, [%0], %1;" :: "r"((uint32_t)(mb)), "r"((uint32_t)(b)) : "memory")
#define MBAR_ARRIVE(mb) \
    asm volatile("mbarrier.arrive.shared.b64 _, [%0];" :: "r"((uint32_t)(mb)) : "memory")

__device__ __forceinline__ void mbar_wait(uint32_t mb, uint32_t parity) {
    asm volatile(
        "{.reg .pred P;\n"
        "W%=:\n"
        "mbarrier.try_wait.parity.acquire.cta.shared::cta.b64 P, [%0], %1, 0x989680;\n"
        "@P bra.uni D%=;\n"
        "bra.uni W%=;\n"
        "D%=:\n}"
        :: "r"(mb), "r"(parity) : "memory");
}

__device__ __forceinline__ void bulkcp(uint32_t dst, const void* src, uint32_t bytes, uint32_t mb) {
    unsigned long long g = (unsigned long long)__cvta_generic_to_global(src);
    asm volatile("cp.async.bulk.shared::cta.global.mbarrier::complete_tx::bytes [%0], [%1], %2, [%3];"
                 :: "r"(dst), "l"(g), "r"(bytes), "r"(mb) : "memory");
}

__device__ __forceinline__ void pfL2(const void* p) {
    asm volatile("prefetch.global.L2 [%0];" :: "l"(p));
}

// pack two fp32 into one half2 register (A-side, single term)
__device__ __forceinline__ uint32_t pack2(float a, float b) {
    __half2 h = __floats2half2_rn(a, b);
    return *reinterpret_cast<uint32_t*>(&h);
}

// Half-GEMM: n-tile-pairs ntp0..ntp0+3, all 8 K-chunks.
// 2-term W-split: acc += Ahi*Whi + Ahi*Wlo  (fp32 accumulate).
__device__ __forceinline__ void gemm_half(
    const uint32_t fhi[8][4],
    uint32_t whi_base, int ntp0, float (*acc)[4])
{
    #pragma unroll
    for (int kc = 0; kc < 8; kc++) {
        #pragma unroll
        for (int i = 0; i < 4; i++) {
            int ntp = ntp0 + i;
            uint32_t ah = whi_base + (uint32_t)(ntp*32 + kc*16*W_PITCH_B);
            uint32_t al = ah + WBUF_B;
            uint32_t h0, h1, h2, h3, l0, l1, l2, l3;
            LDSM_T4(h0, h1, h2, h3, ah);
            LDSM_T4(l0, l1, l2, l3, al);
            int na = 2*i, nb = 2*i + 1;
            MMA16816(acc[na][0],acc[na][1],acc[na][2],acc[na][3],
                     fhi[kc][0],fhi[kc][1],fhi[kc][2],fhi[kc][3], h0,h1);
            MMA16816(acc[nb][0],acc[nb][1],acc[nb][2],acc[nb][3],
                     fhi[kc][0],fhi[kc][1],fhi[kc][2],fhi[kc][3], h2,h3);
            MMA16816(acc[na][0],acc[na][1],acc[na][2],acc[na][3],
                     fhi[kc][0],fhi[kc][1],fhi[kc][2],fhi[kc][3], l0,l1);
            MMA16816(acc[nb][0],acc[nb][1],acc[nb][2],acc[nb][3],
                     fhi[kc][0],fhi[kc][1],fhi[kc][2],fhi[kc][3], l2,l3);
        }
    }
}

// ---------------------------------------------------------------------------
// main fused kernel: 256 threads, 128 rows per CTA
// ---------------------------------------------------------------------------
__global__ void __launch_bounds__(256, 1) msnet_kernel(
    const float* __restrict__ x,
    const float* __restrict__ gammas,
    const float* __restrict__ betas,
    const float* __restrict__ W_pre,
    const float* __restrict__ b_pre,
    const float* __restrict__ b_blocks,
    float* __restrict__ out)
{
    extern __shared__ char smem[];
    uint32_t sb = (uint32_t)__cvta_generic_to_shared(smem);

    int tid  = threadIdx.x;
    int lane = tid & 31;
    int warp = tid >> 5;
    int gr = lane >> 2;            // group row 0..7
    int gc = (lane & 3) * 2;       // group col {0,2,4,6}

    int p0 = blockIdx.x * 128 + warp * 16 + gr;
    int p1 = p0 + 8;

    uint32_t lane_off = (uint32_t)((lane & 15) * W_PITCH_B + (lane >> 4) * 16);

    if (tid == 0) {
        #pragma unroll
        for (int b = 0; b < NBUF; b++) {
            MBAR_INIT(sb + SM_MBAR + b*8, 1);        // FULL[b]
            MBAR_INIT(sb + SM_MBAR + 24 + b*8, 256); // EMPTY[b]
        }
    }

    float* sWpre = (float*)(smem + SM_WPRE);
    float* sBpre = (float*)(smem + SM_BPRE);
    float* sBB   = (float*)(smem + SM_BB);
    for (int i = tid; i < 512; i += 256) sWpre[i] = W_pre[i];
    if (tid < 128) sBpre[tid] = b_pre[tid];
    for (int i = tid; i < NLAY*128; i += 256) sBB[i] = b_blocks[i];
    __syncthreads();   // mbar init + staging visible

    // kick TMA loads for layers 0,1,2
    if (tid == 0) {
        #pragma unroll
        for (int b = 0; b < NBUF; b++) {
            MBAR_EXPECT_TX(sb + SM_MBAR + b*8, WLAYER_B);
            bulkcp(sb + SM_W + (uint32_t)b*WLAYER_B, g_W + (size_t)b*WLAYER_B,
                   WLAYER_B, sb + SM_MBAR + b*8);
        }
    }

    // --- pre-layer: h = sin(x @ Wpre + bpre) ---
    float4 xva = ((const float4*)x)[p0];
    float4 xvb = ((const float4*)x)[p1];
    float xr0[4] = {xva.x, xva.y, xva.z, xva.w};
    float xr1[4] = {xvb.x, xvb.y, xvb.z, xvb.w};

    float h[16][4];
    #pragma unroll
    for (int nt = 0; nt < 16; nt++) {
        int c = nt * 8 + gc;
        float t0 = sBpre[c], t1 = sBpre[c+1];
        float t2 = t0, t3 = t1;
        #pragma unroll
        for (int d = 0; d < 4; d++) {
            float w0 = sWpre[d*128 + c], w1 = sWpre[d*128 + c + 1];
            t0 = fmaf(xr0[d], w0, t0); t1 = fmaf(xr0[d], w1, t1);
            t2 = fmaf(xr1[d], w0, t2); t3 = fmaf(xr1[d], w1, t3);
        }
        h[nt][0] = __sinf(t0); h[nt][1] = __sinf(t1);
        h[nt][2] = __sinf(t2); h[nt][3] = __sinf(t3);
    }

    uint32_t fhi[8][4];

    #pragma unroll 1
    for (int L = 0; L < NLAY; L++) {
        int b = L % 3;
        uint32_t up = (uint32_t)((L / 3) & 1);
        uint32_t FULLb  = sb + SM_MBAR + (uint32_t)b*8;
        uint32_t EMPTYb = sb + SM_MBAR + 24 + (uint32_t)b*8;

        if ((L & 1) == 0) {
            int blk = L >> 1;
            // ---- FiLM: f = gamma*h + beta; h <- f (registers); pack ----
            const float* gP0 = gammas + (size_t)p0 * 1024 + blk * 128;
            const float* gP1 = gammas + (size_t)p1 * 1024 + blk * 128;
            const float* bP0 = betas  + (size_t)p0 * 1024 + blk * 128;
            const float* bP1 = betas  + (size_t)p1 * 1024 + blk * 128;
            #pragma unroll
            for (int nt = 0; nt < 16; nt++) {
                int c = nt * 8 + gc;
                float2 g0 = __ldcs((const float2*)(gP0 + c));
                float2 g1 = __ldcs((const float2*)(gP1 + c));
                float2 e0 = __ldcs((const float2*)(bP0 + c));
                float2 e1 = __ldcs((const float2*)(bP1 + c));
                h[nt][0] = fmaf(g0.x, h[nt][0], e0.x);
                h[nt][1] = fmaf(g0.y, h[nt][1], e0.y);
                h[nt][2] = fmaf(g1.x, h[nt][2], e1.x);
                h[nt][3] = fmaf(g1.y, h[nt][3], e1.y);
                int kc = nt >> 1, e = (nt & 1) * 2;
                fhi[kc][e]   = pack2(h[nt][0], h[nt][1]);
                fhi[kc][e+1] = pack2(h[nt][2], h[nt][3]);
            }
            // L2-prefetch next block's FiLM rows (consumed in ~2 layers)
            if (blk < 7) {
                int co = (lane & 3) * 32;
                pfL2(gammas + (size_t)p0 * 1024 + (blk+1) * 128 + co);
                pfL2(gammas + (size_t)p1 * 1024 + (blk+1) * 128 + co);
                pfL2(betas  + (size_t)p0 * 1024 + (blk+1) * 128 + co);
                pfL2(betas  + (size_t)p1 * 1024 + (blk+1) * 128 + co);
            }
        }

        // ---- bias init from smem ----
        float acc[16][4];
        const float* bias = sBB + L * 128;
        #pragma unroll
        for (int nt = 0; nt < 16; nt++) {
            float2 b2 = *(const float2*)(bias + nt*8 + gc);
            acc[nt][0] = b2.x; acc[nt][1] = b2.y;
            acc[nt][2] = b2.x; acc[nt][3] = b2.y;
        }

        mbar_wait(FULLb, up);
        uint32_t wb = sb + SM_W + (uint32_t)b * WLAYER_B + lane_off;

        // ---- GEMM in two N-halves; half-1 sins interleave half-2 MMAs ----
        gemm_half(fhi, wb, 0, &acc[0]);
        #pragma unroll
        for (int nt = 0; nt < 8; nt++) {
            acc[nt][0] = __sinf(acc[nt][0]); acc[nt][1] = __sinf(acc[nt][1]);
            acc[nt][2] = __sinf(acc[nt][2]); acc[nt][3] = __sinf(acc[nt][3]);
        }
        gemm_half(fhi, wb, 4, &acc[8]);
        MBAR_ARRIVE(EMPTYb);
        #pragma unroll
        for (int nt = 8; nt < 16; nt++) {
            acc[nt][0] = __sinf(acc[nt][0]); acc[nt][1] = __sinf(acc[nt][1]);
            acc[nt][2] = __sinf(acc[nt][2]); acc[nt][3] = __sinf(acc[nt][3]);
        }

        if ((L & 1) == 0) {
            // r1 -> fragments for layer L+1
            #pragma unroll
            for (int nt = 0; nt < 16; nt++) {
                int kc = nt >> 1, e = (nt & 1) * 2;
                fhi[kc][e]   = pack2(acc[nt][0], acc[nt][1]);
                fhi[kc][e+1] = pack2(acc[nt][2], acc[nt][3]);
            }
        } else {
            // residual merge: h = 0.5*(f + r2), f is current h
            #pragma unroll
            for (int nt = 0; nt < 16; nt++) {
                h[nt][0] = 0.5f * (h[nt][0] + acc[nt][0]);
                h[nt][1] = 0.5f * (h[nt][1] + acc[nt][1]);
                h[nt][2] = 0.5f * (h[nt][2] + acc[nt][2]);
                h[nt][3] = 0.5f * (h[nt][3] + acc[nt][3]);
            }
        }

        // refill buffer b with layer L+3 once all warps done reading layer L
        if (tid == 0 && L < NLAY - 3) {
            mbar_wait(EMPTYb, up);
            MBAR_EXPECT_TX(FULLb, WLAYER_B);
            bulkcp(sb + SM_W + (uint32_t)b * WLAYER_B,
                   g_W + (size_t)(L + 3) * WLAYER_B, WLAYER_B, FULLb);
        }
    }

    // ---- write output [N,128] fp32 ----
    #pragma unroll
    for (int nt = 0; nt < 16; nt++) {
        int c = nt * 8 + gc;
        *(float2*)&out[(size_t)p0 * 128 + c] = make_float2(h[nt][0], h[nt][1]);
        *(float2*)&out[(size_t)p1 * 128 + c] = make_float2(h[nt][2], h[nt][3]);
    }
}

// ---------------------------------------------------------------------------
extern "C" void kernel_launch(void* const* d_in, const int* in_sizes, int n_in,
                              void* d_out, int out_size) {
    const float* x        = (const float*)d_in[0];
    const float* gammas   = (const float*)d_in[1];
    const float* betas    = (const float*)d_in[2];
    const float* W_pre    = (const float*)d_in[3];
    const float* b_pre    = (const float*)d_in[4];
    const float* W_blocks = (const float*)d_in[5];
    const float* b_blocks = (const float*)d_in[6];
    float* out = (float*)d_out;

    int N = in_sizes[0] / 4;   // 262144

    msnet_prep_kernel<<<(NLAY*128*128 + 255) / 256, 256>>>(W_blocks);

    cudaFuncSetAttribute(msnet_kernel,
                         cudaFuncAttributeMaxDynamicSharedMemorySize, SMEM_TOTAL);
    msnet_kernel<<<N / 128, 256, SMEM_TOTAL>>>(
        x, gammas, betas, W_pre, b_pre, b_blocks, out);
}

// round 14
// speedup vs baseline: 1.4115x; 1.0100x over previous
#include <cuda_runtime.h>
#include <cuda_fp16.h>
#include <cstdint>

// ---------------------------------------------------------------------------
// MultiShapeNet: h = sin(x@Wpre + bpre); 8 blocks of
//   h = gamma*h + beta;  r = sin(h@W0+b0); r = sin(r@W1+b1); h = 0.5*(h+r)
// N=262144, HIDDEN=128, fp32 in/out, rel_err < 1e-3.
//
// R14: M=32 rows/warp (2 m-tiles) to amortize weight LDSM across 2x rows:
// crossbar was the saturated pipe (L1=81.6%). Each LDSM'd W fragment feeds
// 8 MMAs (was 4). h registers eliminated: merge fuses with next FiLM, and
// the residual f lives in smem as the same fp16 half2 words the fragments
// use (thread-private strided layout, conflict-free). 2-term W-split GEMM
// (r = Ahi*Whi + Ahi*Wlo) as R13. NBUF=2 TMA ring (weights are L2-resident).
// ---------------------------------------------------------------------------

#define NLAY      16
#define WPAD      136           // halves per padded weight row
#define W_PITCH_B (WPAD*2)      // 272 bytes
#define WBUF_B    (128*W_PITCH_B)   // 34816 bytes per (hi or lo) matrix
#define WLAYER_B  (2*WBUF_B)        // 69632 bytes per layer (hi+lo)
#define NBUF      2

// smem layout (bytes)
#define SM_W      0                          // 2 * 69632 = 139264
#define SM_F      (NBUF*WLAYER_B)            // 139264 : 256 rows * 128 fp16 = 65536
#define SM_BB     (SM_F + 65536)             // 204800 : 16*128 fp32 = 8192
#define SM_WPRE   (SM_BB + 8192)             // 212992 : 512 fp32
#define SM_BPRE   (SM_WPRE + 2048)           // 215040 : 128 fp32
#define SM_MBAR   (SM_BPRE + 512)            // 215552 : 4 mbarriers
#define SMEM_TOTAL (SM_MBAR + 64)            // 215616

// weights scratch: [L][hi 34816B][lo 34816B], rows padded to 136 halves
__device__ unsigned char g_W[NLAY * WLAYER_B];

// ---------------------------------------------------------------------------
// prep: W_blocks [16][128][128] fp32 -> fp16 hi/lo, padded rows
// ---------------------------------------------------------------------------
__global__ void msnet_prep_kernel(const float* __restrict__ Wb) {
    int t = blockIdx.x * blockDim.x + threadIdx.x;
    if (t < NLAY*128*128) {
        int L = t >> 14;
        int k = (t >> 7) & 127;
        int n = t & 127;
        float w = Wb[t];
        __half hi = __float2half_rn(w);
        __half lo = __float2half_rn(w - __half2float(hi));
        __half* base = (__half*)(g_W + (size_t)L * WLAYER_B);
        base[k*WPAD + n] = hi;
        base[(WBUF_B/2) + k*WPAD + n] = lo;
    }
    if (t < NLAY*128*8) {        // zero pad columns 128..135
        int L = t >> 10;
        int k = (t >> 3) & 127;
        int n = 128 + (t & 7);
        __half* base = (__half*)(g_W + (size_t)L * WLAYER_B);
        base[k*WPAD + n] = __float2half_rn(0.f);
        base[(WBUF_B/2) + k*WPAD + n] = __float2half_rn(0.f);
    }
}

// ---------------------------------------------------------------------------
// PTX helpers
// ---------------------------------------------------------------------------
#define LDSM_T4(r0,r1,r2,r3,addr) \
    asm volatile("ldmatrix.sync.aligned.m8n8.x4.trans.shared.b16 {%0,%1,%2,%3},[%4];\n" \
                 : "=r"(r0), "=r"(r1), "=r"(r2), "=r"(r3) : "r"(addr))

#define MMA16816(d0,d1,d2,d3,a0,a1,a2,a3,b0,b1) \
    asm volatile("mma.sync.aligned.m16n8k16.row.col.f32.f16.f16.f32 " \
                 "{%0,%1,%2,%3},{%4,%5,%6,%7},{%8,%9},{%0,%1,%2,%3};\n" \
                 : "+f"(d0), "+f"(d1), "+f"(d2), "+f"(d3) \
                 : "r"(a0), "r"(a1), "r"(a2), "r"(a3), "r"(b0), "r"(b1))

#define MBAR_INIT(mb, cnt) \
    asm volatile("mbarrier.init.shared.b64 [%0], %1;" :: "r"((uint32_t)(mb)), "r"((uint32_t)(cnt)) : "memory")
#define MBAR_EXPECT_TX(mb, b) \
    asm volatile("mbarrier.arrive.expect_tx.shared.b64 _, [%0], %1;" :: "r"((uint32_t)(mb)), "r"((uint32_t)(b)) : "memory")
#define MBAR_ARRIVE(mb) \
    asm volatile("mbarrier.arrive.shared.b64 _, [%0];" :: "r"((uint32_t)(mb)) : "memory")

__device__ __forceinline__ void mbar_wait(uint32_t mb, uint32_t parity) {
    asm volatile(
        "{.reg .pred P;\n"
        "W%=:\n"
        "mbarrier.try_wait.parity.acquire.cta.shared::cta.b64 P, [%0], %1, 0x989680;\n"
        "@P bra.uni D%=;\n"
        "bra.uni W%=;\n"
        "D%=:\n}"
        :: "r"(mb), "r"(parity) : "memory");
}

__device__ __forceinline__ void bulkcp(uint32_t dst, const void* src, uint32_t bytes, uint32_t mb) {
    unsigned long long g = (unsigned long long)__cvta_generic_to_global(src);
    asm volatile("cp.async.bulk.shared::cta.global.mbarrier::complete_tx::bytes [%0], [%1], %2, [%3];"
                 :: "r"(dst), "l"(g), "r"(bytes), "r"(mb) : "memory");
}

__device__ __forceinline__ void pfL2(const void* p) {
    asm volatile("prefetch.global.L2 [%0];" :: "l"(p));
}

// pack two fp32 into one half2 register
__device__ __forceinline__ uint32_t pack2(float a, float b) {
    __half2 h = __floats2half2_rn(a, b);
    return *reinterpret_cast<uint32_t*>(&h);
}
__device__ __forceinline__ float2 unpack2(uint32_t u) {
    return __half22float2(*reinterpret_cast<__half2*>(&u));
}

// Half-GEMM over n-tile-pairs NTP0..NTP0+3, all 8 K-chunks, BOTH m-tiles.
// 2-term W-split: acc += Ahi*Whi + Ahi*Wlo (fp32 accumulate).
// Each LDSM'd W fragment pair feeds 8 MMAs (2 mt x 2 nt x 2 terms).
__device__ __forceinline__ void gemm_half(
    const uint32_t f[2][8][4], uint32_t wb, int NTP0, float acc[2][16][4])
{
    #pragma unroll
    for (int kc = 0; kc < 8; kc++) {
        #pragma unroll
        for (int i = 0; i < 4; i++) {
            int ntp = NTP0 + i;
            uint32_t ah = wb + (uint32_t)(ntp*32 + kc*16*W_PITCH_B);
            uint32_t al = ah + WBUF_B;
            uint32_t h0, h1, h2, h3, l0, l1, l2, l3;
            LDSM_T4(h0, h1, h2, h3, ah);
            LDSM_T4(l0, l1, l2, l3, al);
            int na = 2*ntp, nb = 2*ntp + 1;
            #pragma unroll
            for (int mt = 0; mt < 2; mt++) {
                MMA16816(acc[mt][na][0],acc[mt][na][1],acc[mt][na][2],acc[mt][na][3],
                         f[mt][kc][0],f[mt][kc][1],f[mt][kc][2],f[mt][kc][3], h0,h1);
                MMA16816(acc[mt][nb][0],acc[mt][nb][1],acc[mt][nb][2],acc[mt][nb][3],
                         f[mt][kc][0],f[mt][kc][1],f[mt][kc][2],f[mt][kc][3], h2,h3);
                MMA16816(acc[mt][na][0],acc[mt][na][1],acc[mt][na][2],acc[mt][na][3],
                         f[mt][kc][0],f[mt][kc][1],f[mt][kc][2],f[mt][kc][3], l0,l1);
                MMA16816(acc[mt][nb][0],acc[mt][nb][1],acc[mt][nb][2],acc[mt][nb][3],
                         f[mt][kc][0],f[mt][kc][1],f[mt][kc][2],f[mt][kc][3], l2,l3);
            }
        }
    }
}

// ---------------------------------------------------------------------------
// main fused kernel: 256 threads, 256 rows per CTA (32 rows per warp)
// ---------------------------------------------------------------------------
__global__ void __launch_bounds__(256, 1) msnet_kernel(
    const float* __restrict__ x,
    const float* __restrict__ gammas,
    const float* __restrict__ betas,
    const float* __restrict__ W_pre,
    const float* __restrict__ b_pre,
    const float* __restrict__ b_blocks,
    float* __restrict__ out)
{
    extern __shared__ char smem[];
    uint32_t sb = (uint32_t)__cvta_generic_to_shared(smem);

    int tid  = threadIdx.x;
    int lane = tid & 31;
    int warp = tid >> 5;
    int gr = lane >> 2;            // group row 0..7
    int gc = (lane & 3) * 2;       // group col {0,2,4,6}

    // this thread's rows: prow + {0,8} (mt0), prow + {16,24} (mt1)
    size_t prow = (size_t)blockIdx.x * 256 + warp * 32 + gr;

    uint32_t lane_off = (uint32_t)((lane & 15) * W_PITCH_B + (lane >> 4) * 16);

    uint32_t FULL0  = sb + SM_MBAR;
    uint32_t FULL1  = sb + SM_MBAR + 8;
    uint32_t EMPTY0 = sb + SM_MBAR + 16;
    uint32_t EMPTY1 = sb + SM_MBAR + 24;

    if (tid == 0) {
        MBAR_INIT(FULL0, 1);  MBAR_INIT(FULL1, 1);
        MBAR_INIT(EMPTY0, 256); MBAR_INIT(EMPTY1, 256);
    }

    float* sWpre = (float*)(smem + SM_WPRE);
    float* sBpre = (float*)(smem + SM_BPRE);
    float* sBB   = (float*)(smem + SM_BB);
    uint32_t* sF = (uint32_t*)(smem + SM_F);   // per-thread f storage (half2 words)
    for (int i = tid; i < 512; i += 256) sWpre[i] = W_pre[i];
    if (tid < 128) sBpre[tid] = b_pre[tid];
    for (int i = tid; i < NLAY*128; i += 256) sBB[i] = b_blocks[i];
    __syncthreads();   // mbar init + staging visible

    // kick TMA loads for layers 0,1
    if (tid == 0) {
        MBAR_EXPECT_TX(FULL0, WLAYER_B);
        bulkcp(sb + SM_W, g_W, WLAYER_B, FULL0);
        MBAR_EXPECT_TX(FULL1, WLAYER_B);
        bulkcp(sb + SM_W + WLAYER_B, g_W + WLAYER_B, WLAYER_B, FULL1);
    }

    uint32_t fA[2][8][4], fB[2][8][4];

    // --- pre-layer: h = sin(x @ Wpre + bpre), fused with FiLM(block 0) ---
    {
        float xr[4][4];
        #pragma unroll
        for (int rg = 0; rg < 4; rg++) {
            float4 xv = ((const float4*)x)[prow + rg*8];
            xr[rg][0] = xv.x; xr[rg][1] = xv.y; xr[rg][2] = xv.z; xr[rg][3] = xv.w;
        }
        #pragma unroll
        for (int mt = 0; mt < 2; mt++) {
            size_t r0 = prow + mt*16, r1 = r0 + 8;
            #pragma unroll
            for (int nt = 0; nt < 16; nt++) {
                int c = nt * 8 + gc;
                float t0 = sBpre[c], t1 = sBpre[c+1];
                float t2 = t0, t3 = t1;
                #pragma unroll
                for (int d = 0; d < 4; d++) {
                    float w0 = sWpre[d*128 + c], w1 = sWpre[d*128 + c + 1];
                    t0 = fmaf(xr[2*mt][d],   w0, t0); t1 = fmaf(xr[2*mt][d],   w1, t1);
                    t2 = fmaf(xr[2*mt+1][d], w0, t2); t3 = fmaf(xr[2*mt+1][d], w1, t3);
                }
                t0 = __sinf(t0); t1 = __sinf(t1); t2 = __sinf(t2); t3 = __sinf(t3);
                float2 g0 = __ldcs((const float2*)(gammas + r0*1024 + c));
                float2 g1 = __ldcs((const float2*)(gammas + r1*1024 + c));
                float2 e0 = __ldcs((const float2*)(betas  + r0*1024 + c));
                float2 e1 = __ldcs((const float2*)(betas  + r1*1024 + c));
                uint32_t u0 = pack2(fmaf(g0.x, t0, e0.x), fmaf(g0.y, t1, e0.y));
                uint32_t u1 = pack2(fmaf(g1.x, t2, e1.x), fmaf(g1.y, t3, e1.y));
                int kc = nt >> 1, e = (nt & 1) * 2;
                fA[mt][kc][e]   = u0;
                fA[mt][kc][e+1] = u1;
                int fi = (mt*16 + nt) * 2;
                sF[fi*256 + tid]     = u0;
                sF[(fi+1)*256 + tid] = u1;
            }
        }
    }

    #pragma unroll 1
    for (int blk = 0; blk < 8; blk++) {
        uint32_t up = (uint32_t)(blk & 1);

        // ============ even layer L=2blk : fA -> fB (r1) ============
        {
            int L = 2*blk;
            float acc[2][16][4];
            const float* bias = sBB + L * 128;
            #pragma unroll
            for (int nt = 0; nt < 16; nt++) {
                float2 b2 = *(const float2*)(bias + nt*8 + gc);
                #pragma unroll
                for (int mt = 0; mt < 2; mt++) {
                    acc[mt][nt][0] = b2.x; acc[mt][nt][1] = b2.y;
                    acc[mt][nt][2] = b2.x; acc[mt][nt][3] = b2.y;
                }
            }
            mbar_wait(FULL0, up);
            uint32_t wb = sb + SM_W + lane_off;

            gemm_half(fA, wb, 0, acc);
            #pragma unroll
            for (int mt = 0; mt < 2; mt++)
                #pragma unroll
                for (int nt = 0; nt < 8; nt++) {
                    int kc = nt >> 1, e = (nt & 1) * 2;
                    fB[mt][kc][e]   = pack2(__sinf(acc[mt][nt][0]), __sinf(acc[mt][nt][1]));
                    fB[mt][kc][e+1] = pack2(__sinf(acc[mt][nt][2]), __sinf(acc[mt][nt][3]));
                }
            // L2 prefetch next block's FiLM rows (used end of next layer)
            if (blk < 7) {
                int co = (lane & 3) * 32;
                #pragma unroll
                for (int rg = 0; rg < 4; rg++) {
                    pfL2(gammas + (prow + rg*8)*1024 + (size_t)(blk+1)*128 + co);
                    pfL2(betas  + (prow + rg*8)*1024 + (size_t)(blk+1)*128 + co);
                }
            }
            gemm_half(fA, wb, 4, acc);
            MBAR_ARRIVE(EMPTY0);
            #pragma unroll
            for (int mt = 0; mt < 2; mt++)
                #pragma unroll
                for (int nt = 8; nt < 16; nt++) {
                    int kc = nt >> 1, e = (nt & 1) * 2;
                    fB[mt][kc][e]   = pack2(__sinf(acc[mt][nt][0]), __sinf(acc[mt][nt][1]));
                    fB[mt][kc][e+1] = pack2(__sinf(acc[mt][nt][2]), __sinf(acc[mt][nt][3]));
                }
            if (tid == 0 && blk < 7) {
                mbar_wait(EMPTY0, up);
                MBAR_EXPECT_TX(FULL0, WLAYER_B);
                bulkcp(sb + SM_W, g_W + (size_t)(L + 2) * WLAYER_B, WLAYER_B, FULL0);
            }
        }

        // ============ odd layer L=2blk+1 : fB -> fA, merge (+FiLM blk+1) ============
        {
            int L = 2*blk + 1;
            float acc[2][16][4];
            const float* bias = sBB + L * 128;
            #pragma unroll
            for (int nt = 0; nt < 16; nt++) {
                float2 b2 = *(const float2*)(bias + nt*8 + gc);
                #pragma unroll
                for (int mt = 0; mt < 2; mt++) {
                    acc[mt][nt][0] = b2.x; acc[mt][nt][1] = b2.y;
                    acc[mt][nt][2] = b2.x; acc[mt][nt][3] = b2.y;
                }
            }
            mbar_wait(FULL1, up);
            uint32_t wb = sb + SM_W + WLAYER_B + lane_off;

            gemm_half(fB, wb, 0, acc);
            // merge+FiLM for n-tiles 0..7
            if (blk < 7) {
                #pragma unroll
                for (int mt = 0; mt < 2; mt++) {
                    size_t r0 = prow + mt*16, r1 = r0 + 8;
                    #pragma unroll
                    for (int nt = 0; nt < 8; nt++) {
                        int c = nt * 8 + gc;
                        int fi = (mt*16 + nt) * 2;
                        float2 fv0 = unpack2(sF[fi*256 + tid]);
                        float2 fv1 = unpack2(sF[(fi+1)*256 + tid]);
                        float h0 = 0.5f * (fv0.x + __sinf(acc[mt][nt][0]));
                        float h1 = 0.5f * (fv0.y + __sinf(acc[mt][nt][1]));
                        float h2 = 0.5f * (fv1.x + __sinf(acc[mt][nt][2]));
                        float h3 = 0.5f * (fv1.y + __sinf(acc[mt][nt][3]));
                        float2 g0 = __ldcs((const float2*)(gammas + r0*1024 + (size_t)(blk+1)*128 + c));
                        float2 g1 = __ldcs((const float2*)(gammas + r1*1024 + (size_t)(blk+1)*128 + c));
                        float2 e0 = __ldcs((const float2*)(betas  + r0*1024 + (size_t)(blk+1)*128 + c));
                        float2 e1 = __ldcs((const float2*)(betas  + r1*1024 + (size_t)(blk+1)*128 + c));
                        uint32_t u0 = pack2(fmaf(g0.x, h0, e0.x), fmaf(g0.y, h1, e0.y));
                        uint32_t u1 = pack2(fmaf(g1.x, h2, e1.x), fmaf(g1.y, h3, e1.y));
                        int kc = nt >> 1, e = (nt & 1) * 2;
                        fA[mt][kc][e]   = u0;
                        fA[mt][kc][e+1] = u1;
                        sF[fi*256 + tid]     = u0;
                        sF[(fi+1)*256 + tid] = u1;
                    }
                }
            } else {
                #pragma unroll
                for (int mt = 0; mt < 2; mt++) {
                    size_t r0 = prow + mt*16, r1 = r0 + 8;
                    #pragma unroll
                    for (int nt = 0; nt < 8; nt++) {
                        int c = nt * 8 + gc;
                        int fi = (mt*16 + nt) * 2;
                        float2 fv0 = unpack2(sF[fi*256 + tid]);
                        float2 fv1 = unpack2(sF[(fi+1)*256 + tid]);
                        *(float2*)&out[r0*128 + c] = make_float2(
                            0.5f * (fv0.x + __sinf(acc[mt][nt][0])),
                            0.5f * (fv0.y + __sinf(acc[mt][nt][1])));
                        *(float2*)&out[r1*128 + c] = make_float2(
                            0.5f * (fv1.x + __sinf(acc[mt][nt][2])),
                            0.5f * (fv1.y + __sinf(acc[mt][nt][3])));
                    }
                }
            }

            gemm_half(fB, wb, 4, acc);
            MBAR_ARRIVE(EMPTY1);
            // merge+FiLM for n-tiles 8..15
            if (blk < 7) {
                #pragma unroll
                for (int mt = 0; mt < 2; mt++) {
                    size_t r0 = prow + mt*16, r1 = r0 + 8;
                    #pragma unroll
                    for (int nt = 8; nt < 16; nt++) {
                        int c = nt * 8 + gc;
                        int fi = (mt*16 + nt) * 2;
                        float2 fv0 = unpack2(sF[fi*256 + tid]);
                        float2 fv1 = unpack2(sF[(fi+1)*256 + tid]);
                        float h0 = 0.5f * (fv0.x + __sinf(acc[mt][nt][0]));
                        float h1 = 0.5f * (fv0.y + __sinf(acc[mt][nt][1]));
                        float h2 = 0.5f * (fv1.x + __sinf(acc[mt][nt][2]));
                        float h3 = 0.5f * (fv1.y + __sinf(acc[mt][nt][3]));
                        float2 g0 = __ldcs((const float2*)(gammas + r0*1024 + (size_t)(blk+1)*128 + c));
                        float2 g1 = __ldcs((const float2*)(gammas + r1*1024 + (size_t)(blk+1)*128 + c));
                        float2 e0 = __ldcs((const float2*)(betas  + r0*1024 + (size_t)(blk+1)*128 + c));
                        float2 e1 = __ldcs((const float2*)(betas  + r1*1024 + (size_t)(blk+1)*128 + c));
                        uint32_t u0 = pack2(fmaf(g0.x, h0, e0.x), fmaf(g0.y, h1, e0.y));
                        uint32_t u1 = pack2(fmaf(g1.x, h2, e1.x), fmaf(g1.y, h3, e1.y));
                        int kc = nt >> 1, e = (nt & 1) * 2;
                        fA[mt][kc][e]   = u0;
                        fA[mt][kc][e+1] = u1;
                        sF[fi*256 + tid]     = u0;
                        sF[(fi+1)*256 + tid] = u1;
                    }
                }
            } else {
                #pragma unroll
                for (int mt = 0; mt < 2; mt++) {
                    size_t r0 = prow + mt*16, r1 = r0 + 8;
                    #pragma unroll
                    for (int nt = 8; nt < 16; nt++) {
                        int c = nt * 8 + gc;
                        int fi = (mt*16 + nt) * 2;
                        float2 fv0 = unpack2(sF[fi*256 + tid]);
                        float2 fv1 = unpack2(sF[(fi+1)*256 + tid]);
                        *(float2*)&out[r0*128 + c] = make_float2(
                            0.5f * (fv0.x + __sinf(acc[mt][nt][0])),
                            0.5f * (fv0.y + __sinf(acc[mt][nt][1])));
                        *(float2*)&out[r1*128 + c] = make_float2(
                            0.5f * (fv1.x + __sinf(acc[mt][nt][2])),
                            0.5f * (fv1.y + __sinf(acc[mt][nt][3])));
                    }
                }
            }

            if (tid == 0 && blk < 7) {
                mbar_wait(EMPTY1, up);
                MBAR_EXPECT_TX(FULL1, WLAYER_B);
                bulkcp(sb + SM_W + WLAYER_B, g_W + (size_t)(L + 2) * WLAYER_B,
                       WLAYER_B, FULL1);
            }
        }
    }
}

// ---------------------------------------------------------------------------
extern "C" void kernel_launch(void* const* d_in, const int* in_sizes, int n_in,
                              void* d_out, int out_size) {
    const float* x        = (const float*)d_in[0];
    const float* gammas   = (const float*)d_in[1];
    const float* betas    = (const float*)d_in[2];
    const float* W_pre    = (const float*)d_in[3];
    const float* b_pre    = (const float*)d_in[4];
    const float* W_blocks = (const float*)d_in[5];
    const float* b_blocks = (const float*)d_in[6];
    float* out = (float*)d_out;

    int N = in_sizes[0] / 4;   // 262144

    msnet_prep_kernel<<<(NLAY*128*128 + 255) / 256, 256>>>(W_blocks);

    cudaFuncSetAttribute(msnet_kernel,
                         cudaFuncAttributeMaxDynamicSharedMemorySize, SMEM_TOTAL);
    msnet_kernel<<<N / 256, 256, SMEM_TOTAL>>>(
        x, gammas, betas, W_pre, b_pre, b_blocks, out);
}

// round 15
// speedup vs baseline: 1.4780x; 1.0471x over previous
#include <cuda_runtime.h>
#include <cuda_fp16.h>
#include <cstdint>

// ---------------------------------------------------------------------------
// MultiShapeNet: h = sin(x@Wpre + bpre); 8 blocks of
//   h = gamma*h + beta;  r = sin(h@W0+b0); r = sin(r@W1+b1); h = 0.5*(h+r)
// N=262144, HIDDEN=128, fp32 in/out, rel_err < 1e-3.
//
// R15: single-term fp16 GEMM: r = fp16(A) * fp16(W), fp32 accumulate.
// Calibrated error model (R12/R13/R14 measurements) predicts ~4.4e-4 total.
// Residual f stored fp32 in smem (reclaims R14's fp16-residual penalty) in
// the space freed by dropping Wlo. MMAs, LDSM, and TMA bytes all halve vs
// R14; overlap structure (M=32/warp, 2-buffer TMA ring, fused FiLM) kept.
// ---------------------------------------------------------------------------

#define NLAY      16
#define WPAD      136           // halves per padded weight row
#define W_PITCH_B (WPAD*2)      // 272 bytes
#define WBUF_B    (128*W_PITCH_B)   // 34816 bytes per layer (fp16 W)
#define NBUF      2

// smem layout (bytes)
#define SM_W      0                          // 2 * 34816 = 69632
#define SM_F      (NBUF*WBUF_B)              // 69632 : 256 rows * 128 fp32 = 131072
#define SM_BB     (SM_F + 131072)            // 200704 : 16*128 fp32 = 8192
#define SM_WPRE   (SM_BB + 8192)             // 208896 : 512 fp32
#define SM_BPRE   (SM_WPRE + 2048)           // 210944 : 128 fp32
#define SM_MBAR   (SM_BPRE + 512)            // 211456 : 4 mbarriers
#define SMEM_TOTAL (SM_MBAR + 64)            // 211520

// weights scratch: [L][fp16 34816B], rows padded to 136 halves
__device__ unsigned char g_W[NLAY * WBUF_B];

// ---------------------------------------------------------------------------
// prep: W_blocks [16][128][128] fp32 -> fp16, padded rows
// ---------------------------------------------------------------------------
__global__ void msnet_prep_kernel(const float* __restrict__ Wb) {
    int t = blockIdx.x * blockDim.x + threadIdx.x;
    if (t < NLAY*128*128) {
        int L = t >> 14;
        int k = (t >> 7) & 127;
        int n = t & 127;
        __half* base = (__half*)(g_W + (size_t)L * WBUF_B);
        base[k*WPAD + n] = __float2half_rn(Wb[t]);
    }
    if (t < NLAY*128*8) {        // zero pad columns 128..135
        int L = t >> 10;
        int k = (t >> 3) & 127;
        int n = 128 + (t & 7);
        __half* base = (__half*)(g_W + (size_t)L * WBUF_B);
        base[k*WPAD + n] = __float2half_rn(0.f);
    }
}

// ---------------------------------------------------------------------------
// PTX helpers
// ---------------------------------------------------------------------------
#define LDSM_T4(r0,r1,r2,r3,addr) \
    asm volatile("ldmatrix.sync.aligned.m8n8.x4.trans.shared.b16 {%0,%1,%2,%3},[%4];\n" \
                 : "=r"(r0), "=r"(r1), "=r"(r2), "=r"(r3) : "r"(addr))

#define MMA16816(d0,d1,d2,d3,a0,a1,a2,a3,b0,b1) \
    asm volatile("mma.sync.aligned.m16n8k16.row.col.f32.f16.f16.f32 " \
                 "{%0,%1,%2,%3},{%4,%5,%6,%7},{%8,%9},{%0,%1,%2,%3};\n" \
                 : "+f"(d0), "+f"(d1), "+f"(d2), "+f"(d3) \
                 : "r"(a0), "r"(a1), "r"(a2), "r"(a3), "r"(b0), "r"(b1))

#define MBAR_INIT(mb, cnt) \
    asm volatile("mbarrier.init.shared.b64 [%0], %1;" :: "r"((uint32_t)(mb)), "r"((uint32_t)(cnt)) : "memory")
#define MBAR_EXPECT_TX(mb, b) \
    asm volatile("mbarrier.arrive.expect_tx.shared.b64 _, [%0], %1;" :: "r"((uint32_t)(mb)), "r"((uint32_t)(b)) : "memory")
#define MBAR_ARRIVE(mb) \
    asm volatile("mbarrier.arrive.shared.b64 _, [%0];" :: "r"((uint32_t)(mb)) : "memory")

__device__ __forceinline__ void mbar_wait(uint32_t mb, uint32_t parity) {
    asm volatile(
        "{.reg .pred P;\n"
        "W%=:\n"
        "mbarrier.try_wait.parity.acquire.cta.shared::cta.b64 P, [%0], %1, 0x989680;\n"
        "@P bra.uni D%=;\n"
        "bra.uni W%=;\n"
        "D%=:\n}"
        :: "r"(mb), "r"(parity) : "memory");
}

__device__ __forceinline__ void bulkcp(uint32_t dst, const void* src, uint32_t bytes, uint32_t mb) {
    unsigned long long g = (unsigned long long)__cvta_generic_to_global(src);
    asm volatile("cp.async.bulk.shared::cta.global.mbarrier::complete_tx::bytes [%0], [%1], %2, [%3];"
                 :: "r"(dst), "l"(g), "r"(bytes), "r"(mb) : "memory");
}

__device__ __forceinline__ void pfL2(const void* p) {
    asm volatile("prefetch.global.L2 [%0];" :: "l"(p));
}

// pack two fp32 into one half2 register
__device__ __forceinline__ uint32_t pack2(float a, float b) {
    __half2 h = __floats2half2_rn(a, b);
    return *reinterpret_cast<uint32_t*>(&h);
}

// Half-GEMM over n-tile-pairs NTP0..NTP0+3, all 8 K-chunks, BOTH m-tiles.
// Single-term: acc += fp16(A) * fp16(W), fp32 accumulate.
// Each LDSM'd W fragment feeds 4 MMAs (2 mt x 2 nt).
__device__ __forceinline__ void gemm_half(
    const uint32_t f[2][8][4], uint32_t wb, int NTP0, float acc[2][16][4])
{
    #pragma unroll
    for (int kc = 0; kc < 8; kc++) {
        #pragma unroll
        for (int i = 0; i < 4; i++) {
            int ntp = NTP0 + i;
            uint32_t ah = wb + (uint32_t)(ntp*32 + kc*16*W_PITCH_B);
            uint32_t h0, h1, h2, h3;
            LDSM_T4(h0, h1, h2, h3, ah);
            int na = 2*ntp, nb = 2*ntp + 1;
            #pragma unroll
            for (int mt = 0; mt < 2; mt++) {
                MMA16816(acc[mt][na][0],acc[mt][na][1],acc[mt][na][2],acc[mt][na][3],
                         f[mt][kc][0],f[mt][kc][1],f[mt][kc][2],f[mt][kc][3], h0,h1);
                MMA16816(acc[mt][nb][0],acc[mt][nb][1],acc[mt][nb][2],acc[mt][nb][3],
                         f[mt][kc][0],f[mt][kc][1],f[mt][kc][2],f[mt][kc][3], h2,h3);
            }
        }
    }
}

// ---------------------------------------------------------------------------
// main fused kernel: 256 threads, 256 rows per CTA (32 rows per warp)
// ---------------------------------------------------------------------------
__global__ void __launch_bounds__(256, 1) msnet_kernel(
    const float* __restrict__ x,
    const float* __restrict__ gammas,
    const float* __restrict__ betas,
    const float* __restrict__ W_pre,
    const float* __restrict__ b_pre,
    const float* __restrict__ b_blocks,
    float* __restrict__ out)
{
    extern __shared__ char smem[];
    uint32_t sb = (uint32_t)__cvta_generic_to_shared(smem);

    int tid  = threadIdx.x;
    int lane = tid & 31;
    int warp = tid >> 5;
    int gr = lane >> 2;            // group row 0..7
    int gc = (lane & 3) * 2;       // group col {0,2,4,6}

    // this thread's rows: prow + {0,8} (mt0), prow + {16,24} (mt1)
    size_t prow = (size_t)blockIdx.x * 256 + warp * 32 + gr;

    uint32_t lane_off = (uint32_t)((lane & 15) * W_PITCH_B + (lane >> 4) * 16);

    uint32_t FULL0  = sb + SM_MBAR;
    uint32_t FULL1  = sb + SM_MBAR + 8;
    uint32_t EMPTY0 = sb + SM_MBAR + 16;
    uint32_t EMPTY1 = sb + SM_MBAR + 24;

    if (tid == 0) {
        MBAR_INIT(FULL0, 1);  MBAR_INIT(FULL1, 1);
        MBAR_INIT(EMPTY0, 256); MBAR_INIT(EMPTY1, 256);
    }

    float* sWpre = (float*)(smem + SM_WPRE);
    float* sBpre = (float*)(smem + SM_BPRE);
    float* sBB   = (float*)(smem + SM_BB);
    float2* sF2  = (float2*)(smem + SM_F);   // per-thread fp32 residual storage
    for (int i = tid; i < 512; i += 256) sWpre[i] = W_pre[i];
    if (tid < 128) sBpre[tid] = b_pre[tid];
    for (int i = tid; i < NLAY*128; i += 256) sBB[i] = b_blocks[i];
    __syncthreads();   // mbar init + staging visible

    // kick TMA loads for layers 0,1
    if (tid == 0) {
        MBAR_EXPECT_TX(FULL0, WBUF_B);
        bulkcp(sb + SM_W, g_W, WBUF_B, FULL0);
        MBAR_EXPECT_TX(FULL1, WBUF_B);
        bulkcp(sb + SM_W + WBUF_B, g_W + WBUF_B, WBUF_B, FULL1);
    }

    uint32_t fA[2][8][4], fB[2][8][4];

    // --- pre-layer: h = sin(x @ Wpre + bpre), fused with FiLM(block 0) ---
    {
        float xr[4][4];
        #pragma unroll
        for (int rg = 0; rg < 4; rg++) {
            float4 xv = ((const float4*)x)[prow + rg*8];
            xr[rg][0] = xv.x; xr[rg][1] = xv.y; xr[rg][2] = xv.z; xr[rg][3] = xv.w;
        }
        #pragma unroll
        for (int mt = 0; mt < 2; mt++) {
            size_t r0 = prow + mt*16, r1 = r0 + 8;
            #pragma unroll
            for (int nt = 0; nt < 16; nt++) {
                int c = nt * 8 + gc;
                float t0 = sBpre[c], t1 = sBpre[c+1];
                float t2 = t0, t3 = t1;
                #pragma unroll
                for (int d = 0; d < 4; d++) {
                    float w0 = sWpre[d*128 + c], w1 = sWpre[d*128 + c + 1];
                    t0 = fmaf(xr[2*mt][d],   w0, t0); t1 = fmaf(xr[2*mt][d],   w1, t1);
                    t2 = fmaf(xr[2*mt+1][d], w0, t2); t3 = fmaf(xr[2*mt+1][d], w1, t3);
                }
                t0 = __sinf(t0); t1 = __sinf(t1); t2 = __sinf(t2); t3 = __sinf(t3);
                float2 g0 = __ldcs((const float2*)(gammas + r0*1024 + c));
                float2 g1 = __ldcs((const float2*)(gammas + r1*1024 + c));
                float2 e0 = __ldcs((const float2*)(betas  + r0*1024 + c));
                float2 e1 = __ldcs((const float2*)(betas  + r1*1024 + c));
                float f0 = fmaf(g0.x, t0, e0.x), f1 = fmaf(g0.y, t1, e0.y);
                float f2 = fmaf(g1.x, t2, e1.x), f3 = fmaf(g1.y, t3, e1.y);
                int kc = nt >> 1, e = (nt & 1) * 2;
                fA[mt][kc][e]   = pack2(f0, f1);
                fA[mt][kc][e+1] = pack2(f2, f3);
                int fi = (mt*16 + nt) * 2;
                sF2[fi*256 + tid]     = make_float2(f0, f1);
                sF2[(fi+1)*256 + tid] = make_float2(f2, f3);
            }
        }
    }

    #pragma unroll 1
    for (int blk = 0; blk < 8; blk++) {
        uint32_t up = (uint32_t)(blk & 1);

        // ============ even layer L=2blk : fA -> fB (r1) ============
        {
            int L = 2*blk;
            float acc[2][16][4];
            const float* bias = sBB + L * 128;
            #pragma unroll
            for (int nt = 0; nt < 16; nt++) {
                float2 b2 = *(const float2*)(bias + nt*8 + gc);
                #pragma unroll
                for (int mt = 0; mt < 2; mt++) {
                    acc[mt][nt][0] = b2.x; acc[mt][nt][1] = b2.y;
                    acc[mt][nt][2] = b2.x; acc[mt][nt][3] = b2.y;
                }
            }
            mbar_wait(FULL0, up);
            uint32_t wb = sb + SM_W + lane_off;

            gemm_half(fA, wb, 0, acc);
            #pragma unroll
            for (int mt = 0; mt < 2; mt++)
                #pragma unroll
                for (int nt = 0; nt < 8; nt++) {
                    int kc = nt >> 1, e = (nt & 1) * 2;
                    fB[mt][kc][e]   = pack2(__sinf(acc[mt][nt][0]), __sinf(acc[mt][nt][1]));
                    fB[mt][kc][e+1] = pack2(__sinf(acc[mt][nt][2]), __sinf(acc[mt][nt][3]));
                }
            // L2 prefetch next block's FiLM rows (used end of next layer)
            if (blk < 7) {
                int co = (lane & 3) * 32;
                #pragma unroll
                for (int rg = 0; rg < 4; rg++) {
                    pfL2(gammas + (prow + rg*8)*1024 + (size_t)(blk+1)*128 + co);
                    pfL2(betas  + (prow + rg*8)*1024 + (size_t)(blk+1)*128 + co);
                }
            }
            gemm_half(fA, wb, 4, acc);
            MBAR_ARRIVE(EMPTY0);
            #pragma unroll
            for (int mt = 0; mt < 2; mt++)
                #pragma unroll
                for (int nt = 8; nt < 16; nt++) {
                    int kc = nt >> 1, e = (nt & 1) * 2;
                    fB[mt][kc][e]   = pack2(__sinf(acc[mt][nt][0]), __sinf(acc[mt][nt][1]));
                    fB[mt][kc][e+1] = pack2(__sinf(acc[mt][nt][2]), __sinf(acc[mt][nt][3]));
                }
            if (tid == 0 && blk < 7) {
                mbar_wait(EMPTY0, up);
                MBAR_EXPECT_TX(FULL0, WBUF_B);
                bulkcp(sb + SM_W, g_W + (size_t)(L + 2) * WBUF_B, WBUF_B, FULL0);
            }
        }

        // ============ odd layer L=2blk+1 : fB -> fA, merge (+FiLM blk+1) ============
        {
            int L = 2*blk + 1;
            float acc[2][16][4];
            const float* bias = sBB + L * 128;
            #pragma unroll
            for (int nt = 0; nt < 16; nt++) {
                float2 b2 = *(const float2*)(bias + nt*8 + gc);
                #pragma unroll
                for (int mt = 0; mt < 2; mt++) {
                    acc[mt][nt][0] = b2.x; acc[mt][nt][1] = b2.y;
                    acc[mt][nt][2] = b2.x; acc[mt][nt][3] = b2.y;
                }
            }
            mbar_wait(FULL1, up);
            uint32_t wb = sb + SM_W + WBUF_B + lane_off;

            gemm_half(fB, wb, 0, acc);
            // merge+FiLM for n-tiles 0..7
            if (blk < 7) {
                #pragma unroll
                for (int mt = 0; mt < 2; mt++) {
                    size_t r0 = prow + mt*16, r1 = r0 + 8;
                    #pragma unroll
                    for (int nt = 0; nt < 8; nt++) {
                        int c = nt * 8 + gc;
                        int fi = (mt*16 + nt) * 2;
                        float2 fv0 = sF2[fi*256 + tid];
                        float2 fv1 = sF2[(fi+1)*256 + tid];
                        float h0 = 0.5f * (fv0.x + __sinf(acc[mt][nt][0]));
                        float h1 = 0.5f * (fv0.y + __sinf(acc[mt][nt][1]));
                        float h2 = 0.5f * (fv1.x + __sinf(acc[mt][nt][2]));
                        float h3 = 0.5f * (fv1.y + __sinf(acc[mt][nt][3]));
                        float2 g0 = __ldcs((const float2*)(gammas + r0*1024 + (size_t)(blk+1)*128 + c));
                        float2 g1 = __ldcs((const float2*)(gammas + r1*1024 + (size_t)(blk+1)*128 + c));
                        float2 e0 = __ldcs((const float2*)(betas  + r0*1024 + (size_t)(blk+1)*128 + c));
                        float2 e1 = __ldcs((const float2*)(betas  + r1*1024 + (size_t)(blk+1)*128 + c));
                        float f0 = fmaf(g0.x, h0, e0.x), f1 = fmaf(g0.y, h1, e0.y);
                        float f2 = fmaf(g1.x, h2, e1.x), f3 = fmaf(g1.y, h3, e1.y);
                        int kc = nt >> 1, e = (nt & 1) * 2;
                        fA[mt][kc][e]   = pack2(f0, f1);
                        fA[mt][kc][e+1] = pack2(f2, f3);
                        sF2[fi*256 + tid]     = make_float2(f0, f1);
                        sF2[(fi+1)*256 + tid] = make_float2(f2, f3);
                    }
                }
            } else {
                #pragma unroll
                for (int mt = 0; mt < 2; mt++) {
                    size_t r0 = prow + mt*16, r1 = r0 + 8;
                    #pragma unroll
                    for (int nt = 0; nt < 8; nt++) {
                        int c = nt * 8 + gc;
                        int fi = (mt*16 + nt) * 2;
                        float2 fv0 = sF2[fi*256 + tid];
                        float2 fv1 = sF2[(fi+1)*256 + tid];
                        *(float2*)&out[r0*128 + c] = make_float2(
                            0.5f * (fv0.x + __sinf(acc[mt][nt][0])),
                            0.5f * (fv0.y + __sinf(acc[mt][nt][1])));
                        *(float2*)&out[r1*128 + c] = make_float2(
                            0.5f * (fv1.x + __sinf(acc[mt][nt][2])),
                            0.5f * (fv1.y + __sinf(acc[mt][nt][3])));
                    }
                }
            }

            gemm_half(fB, wb, 4, acc);
            MBAR_ARRIVE(EMPTY1);
            // merge+FiLM for n-tiles 8..15
            if (blk < 7) {
                #pragma unroll
                for (int mt = 0; mt < 2; mt++) {
                    size_t r0 = prow + mt*16, r1 = r0 + 8;
                    #pragma unroll
                    for (int nt = 8; nt < 16; nt++) {
                        int c = nt * 8 + gc;
                        int fi = (mt*16 + nt) * 2;
                        float2 fv0 = sF2[fi*256 + tid];
                        float2 fv1 = sF2[(fi+1)*256 + tid];
                        float h0 = 0.5f * (fv0.x + __sinf(acc[mt][nt][0]));
                        float h1 = 0.5f * (fv0.y + __sinf(acc[mt][nt][1]));
                        float h2 = 0.5f * (fv1.x + __sinf(acc[mt][nt][2]));
                        float h3 = 0.5f * (fv1.y + __sinf(acc[mt][nt][3]));
                        float2 g0 = __ldcs((const float2*)(gammas + r0*1024 + (size_t)(blk+1)*128 + c));
                        float2 g1 = __ldcs((const float2*)(gammas + r1*1024 + (size_t)(blk+1)*128 + c));
                        float2 e0 = __ldcs((const float2*)(betas  + r0*1024 + (size_t)(blk+1)*128 + c));
                        float2 e1 = __ldcs((const float2*)(betas  + r1*1024 + (size_t)(blk+1)*128 + c));
                        float f0 = fmaf(g0.x, h0, e0.x), f1 = fmaf(g0.y, h1, e0.y);
                        float f2 = fmaf(g1.x, h2, e1.x), f3 = fmaf(g1.y, h3, e1.y);
                        int kc = nt >> 1, e = (nt & 1) * 2;
                        fA[mt][kc][e]   = pack2(f0, f1);
                        fA[mt][kc][e+1] = pack2(f2, f3);
                        sF2[fi*256 + tid]     = make_float2(f0, f1);
                        sF2[(fi+1)*256 + tid] = make_float2(f2, f3);
                    }
                }
            } else {
                #pragma unroll
                for (int mt = 0; mt < 2; mt++) {
                    size_t r0 = prow + mt*16, r1 = r0 + 8;
                    #pragma unroll
                    for (int nt = 8; nt < 16; nt++) {
                        int c = nt * 8 + gc;
                        int fi = (mt*16 + nt) * 2;
                        float2 fv0 = sF2[fi*256 + tid];
                        float2 fv1 = sF2[(fi+1)*256 + tid];
                        *(float2*)&out[r0*128 + c] = make_float2(
                            0.5f * (fv0.x + __sinf(acc[mt][nt][0])),
                            0.5f * (fv0.y + __sinf(acc[mt][nt][1])));
                        *(float2*)&out[r1*128 + c] = make_float2(
                            0.5f * (fv1.x + __sinf(acc[mt][nt][2])),
                            0.5f * (fv1.y + __sinf(acc[mt][nt][3])));
                    }
                }
            }

            if (tid == 0 && blk < 7) {
                mbar_wait(EMPTY1, up);
                MBAR_EXPECT_TX(FULL1, WBUF_B);
                bulkcp(sb + SM_W + WBUF_B, g_W + (size_t)(L + 2) * WBUF_B,
                       WBUF_B, FULL1);
            }
        }
    }
}

// ---------------------------------------------------------------------------
extern "C" void kernel_launch(void* const* d_in, const int* in_sizes, int n_in,
                              void* d_out, int out_size) {
    const float* x        = (const float*)d_in[0];
    const float* gammas   = (const float*)d_in[1];
    const float* betas    = (const float*)d_in[2];
    const float* W_pre    = (const float*)d_in[3];
    const float* b_pre    = (const float*)d_in[4];
    const float* W_blocks = (const float*)d_in[5];
    const float* b_blocks = (const float*)d_in[6];
    float* out = (float*)d_out;

    int N = in_sizes[0] / 4;   // 262144

    msnet_prep_kernel<<<(NLAY*128*128 + 255) / 256, 256>>>(W_blocks);

    cudaFuncSetAttribute(msnet_kernel,
                         cudaFuncAttributeMaxDynamicSharedMemorySize, SMEM_TOTAL);
    msnet_kernel<<<N / 256, 256, SMEM_TOTAL>>>(
        x, gammas, betas, W_pre, b_pre, b_blocks, out);
}